// round 8
// baseline (speedup 1.0000x reference)
#include <cuda_runtime.h>
#include <cuda.h>
#include <cuda_fp16.h>
#include <cstdint>

#define MROWS   8192
#define UNITS   4096
#define INFEAT  4096

// GEMM tiling: CTA 128x128x64, 8 compute warps (2x4, warp tile 64x32) + 1 TMA warp
#define CTAM 128
#define CTAN 128
#define KC   64
#define NSTAGE 4
#define STAGE_A_BYTES 16384          // 128 rows x 128B
#define STAGE_BYTES   32768          // A + B
#define SMEM_BYTES (1024 + NSTAGE * STAGE_BYTES)
#define NTHREADS 288

// Scratch (allocation-free rule: __device__ globals)
__device__ __align__(1024) __half g_Xh[(size_t)MROWS * INFEAT];   // 64 MB
__device__ __align__(1024) __half g_Wh[(size_t)UNITS * INFEAT];   // 32 MB

// ---------------------------------------------------------------- utilities
static __device__ __forceinline__ uint32_t smem_u32(const void* p) {
    uint32_t a;
    asm("{ .reg .u64 t; cvta.to.shared.u64 t, %1; cvt.u32.u64 %0, t; }"
        : "=r"(a) : "l"(p));
    return a;
}

#define MBARRIER_INIT(addr, cnt) \
    asm volatile("mbarrier.init.shared.b64 [%0], %1;" :: "r"(addr), "r"(cnt) : "memory")
#define MBARRIER_EXPECT_TX(addr, bytes) \
    asm volatile("mbarrier.arrive.expect_tx.shared.b64 _, [%0], %1;" \
                 :: "r"(addr), "r"(bytes) : "memory")
#define MBARRIER_ARRIVE(addr) \
    asm volatile("mbarrier.arrive.shared.b64 _, [%0];" :: "r"(addr) : "memory")

static __device__ __forceinline__ void mbar_wait(uint32_t addr, uint32_t parity) {
    asm volatile(
        "{\n\t.reg .pred P;\n\t"
        "LAB_WAIT_%=:\n\t"
        "mbarrier.try_wait.parity.acquire.cta.shared::cta.b64 P, [%0], %1, 0x989680;\n\t"
        "@P bra.uni LAB_DONE_%=;\n\t"
        "bra.uni LAB_WAIT_%=;\n\t"
        "LAB_DONE_%=:\n\t}"
        :: "r"(addr), "r"(parity) : "memory");
}

static __device__ __forceinline__ void tma2d(uint32_t dst, const CUtensorMap* tm,
                                             int cx, int cy, uint32_t mbar) {
    asm volatile(
        "cp.async.bulk.tensor.2d.shared::cta.global.tile.mbarrier::complete_tx::bytes "
        "[%0], [%1, {%2, %3}], [%4];"
        :: "r"(dst), "l"(tm), "r"(cx), "r"(cy), "r"(mbar) : "memory");
}

#define LDSM_X4(r0, r1, r2, r3, a) \
    asm volatile("ldmatrix.sync.aligned.m8n8.x4.shared.b16 {%0,%1,%2,%3}, [%4];" \
                 : "=r"(r0), "=r"(r1), "=r"(r2), "=r"(r3) : "r"(a))

#define MMA16816(c, a0, a1, a2, a3, b0, b1) \
    asm volatile("mma.sync.aligned.m16n8k16.row.col.f32.f16.f16.f32 " \
                 "{%0,%1,%2,%3}, {%4,%5,%6,%7}, {%8,%9}, {%0,%1,%2,%3};" \
                 : "+f"((c)[0]), "+f"((c)[1]), "+f"((c)[2]), "+f"((c)[3]) \
                 : "r"(a0), "r"(a1), "r"(a2), "r"(a3), "r"(b0), "r"(b1))

// ---------------------------------------------------------------- prep kernels

// x fp32 -> fp16 (33.5M elems, 4/thread)
__global__ void cvt_x_kernel(const float4* __restrict__ x) {
    int i = blockIdx.x * blockDim.x + threadIdx.x;
    float4 v = x[i];
    __half2 a = __floats2half2_rn(v.x, v.y);
    __half2 b = __floats2half2_rn(v.z, v.w);
    uint2 o;
    o.x = *reinterpret_cast<uint32_t*>(&a);
    o.y = *reinterpret_cast<uint32_t*>(&b);
    reinterpret_cast<uint2*>(g_Xh)[i] = o;
}

// Unpack 2-bit ternary planes -> fp16 W[u][i].
// pw arrives as int32 (harness upcasts uint8): ONE packed byte per 32-bit word.
// w[u][i] = ((pw32[(u%1024)*4096 + i] >> (2*(u/1024))) & 3) - 1
__global__ void unpack_w_kernel(const int4* __restrict__ pw) {
    int t  = blockIdx.x * blockDim.x + threadIdx.x;   // 0 .. 4194303 (4 halfs each)
    int u  = t >> 10;
    int sh = (u >> 10) * 2;
    int4 v = pw[((u & 1023) << 10) + (t & 1023)];     // 4 packed bytes (as int32s)
    const uint64_t LUT = 0x40003C000000BC00ull;       // {-1,0,1,2} as fp16
    uint32_t c0 = ((uint32_t)v.x >> sh) & 3;
    uint32_t c1 = ((uint32_t)v.y >> sh) & 3;
    uint32_t c2 = ((uint32_t)v.z >> sh) & 3;
    uint32_t c3 = ((uint32_t)v.w >> sh) & 3;
    uint32_t lo = (uint32_t)((LUT >> (c0 << 4)) & 0xFFFF) |
                  ((uint32_t)((LUT >> (c1 << 4)) & 0xFFFF) << 16);
    uint32_t hi = (uint32_t)((LUT >> (c2 << 4)) & 0xFFFF) |
                  ((uint32_t)((LUT >> (c3 << 4)) & 0xFFFF) << 16);
    reinterpret_cast<uint2*>(g_Wh)[t] = make_uint2(lo, hi);
}

// ---------------------------------------------------------------- GEMM kernel
__global__ void __launch_bounds__(NTHREADS, 1) gemm_kernel(
    const __grid_constant__ CUtensorMap tmA,
    const __grid_constant__ CUtensorMap tmB,
    const float* __restrict__ scale, const float* __restrict__ bias,
    float* __restrict__ out)
{
    extern __shared__ __align__(1024) char smem[];
    const uint32_t sb = smem_u32(smem);
    const int tid = threadIdx.x, wid = tid >> 5, lane = tid & 31;
    const int m_base = blockIdx.x * CTAM, n_base = blockIdx.y * CTAN;

    const uint32_t FULL0 = sb, EMPTY0 = sb + 64, STAGE0 = sb + 1024;

    if (tid == 0) {
        for (int s = 0; s < NSTAGE; s++) {
            MBARRIER_INIT(FULL0 + 8 * s, 1);
            MBARRIER_INIT(EMPTY0 + 8 * s, 256);   // 8 compute warps arrive
        }
        asm volatile("fence.proxy.async.shared::cta;" ::: "memory");
    }
    __syncthreads();

    if (wid == 8) {
        // ---- producer: TMA warp ----
        if (lane == 0) {
            for (int i = 0; i < 64; i++) {
                int s = i & 3;
                if (i >= NSTAGE) mbar_wait(EMPTY0 + 8 * s, ((i >> 2) + 1) & 1);
                MBARRIER_EXPECT_TX(FULL0 + 8 * s, STAGE_BYTES);
                uint32_t dst = STAGE0 + s * STAGE_BYTES;
                tma2d(dst,                 &tmA, i * KC, m_base, FULL0 + 8 * s);
                tma2d(dst + STAGE_A_BYTES, &tmB, i * KC, n_base, FULL0 + 8 * s);
            }
        }
        return;
    }

    // ---- compute warps 0-7, warp tile 64x32 at (mw*64, nw*32) ----
    const int mw = wid >> 2, nw = wid & 3;
    const int m0 = mw * 64, n0 = nw * 32;

    // ldmatrix lane address components (SW128 at 128B pitch: addr ^= (row&7)<<4)
    const int rowA  = lane & 15;            // + m0 + mi*16
    const int coffA = (lane >> 4) << 4;     // byte col within 32B k16-slab
    const int swzA  = (rowA & 7) << 4;
    const int rowB  = (((lane >> 4) & 1) << 3) + (lane & 7);  // + n0 + nj*16
    const int coffB = ((lane >> 3) & 1) << 4;
    const int swzB  = (rowB & 7) << 4;

    float acc[4][4][4];
#pragma unroll
    for (int mi = 0; mi < 4; mi++)
#pragma unroll
        for (int ni = 0; ni < 4; ni++)
#pragma unroll
            for (int e = 0; e < 4; e++) acc[mi][ni][e] = 0.f;

    for (int i = 0; i < 64; i++) {
        int s = i & 3;
        mbar_wait(FULL0 + 8 * s, (i >> 2) & 1);
        uint32_t aBase = STAGE0 + s * STAGE_BYTES;
        uint32_t bBase = aBase + STAGE_A_BYTES;
#pragma unroll
        for (int k16 = 0; k16 < 4; k16++) {
            uint32_t a[4][4], b[2][4];
#pragma unroll
            for (int mi = 0; mi < 4; mi++) {
                uint32_t ad = aBase + (m0 + mi * 16 + rowA) * 128 +
                              ((k16 * 32 + coffA) ^ swzA);
                LDSM_X4(a[mi][0], a[mi][1], a[mi][2], a[mi][3], ad);
            }
#pragma unroll
            for (int nj = 0; nj < 2; nj++) {
                uint32_t bd = bBase + (n0 + nj * 16 + rowB) * 128 +
                              ((k16 * 32 + coffB) ^ swzB);
                LDSM_X4(b[nj][0], b[nj][1], b[nj][2], b[nj][3], bd);
            }
#pragma unroll
            for (int mi = 0; mi < 4; mi++) {
#pragma unroll
                for (int ni = 0; ni < 4; ni++) {
                    const uint32_t* bf = &b[ni >> 1][(ni & 1) << 1];
                    MMA16816(acc[mi][ni], a[mi][0], a[mi][1], a[mi][2], a[mi][3],
                             bf[0], bf[1]);
                }
            }
        }
        MBARRIER_ARRIVE(EMPTY0 + 8 * s);
    }

    // ---- epilogue: scale/bias/clip, direct to gmem ----
    const int gr = lane >> 2, tc = (lane & 3) << 1;
    float2 sv[4], bv[4];
#pragma unroll
    for (int ni = 0; ni < 4; ni++) {
        int col = n_base + n0 + ni * 8 + tc;
        sv[ni] = __ldg((const float2*)(scale + col));
        bv[ni] = __ldg((const float2*)(bias + col));
    }
#pragma unroll
    for (int mi = 0; mi < 4; mi++) {
        int row0 = m_base + m0 + mi * 16 + gr;
#pragma unroll
        for (int ni = 0; ni < 4; ni++) {
            int col = n_base + n0 + ni * 8 + tc;
            float2 o0, o1;
            o0.x = fminf(fmaxf(acc[mi][ni][0] * sv[ni].x + bv[ni].x, -100.f), 100.f);
            o0.y = fminf(fmaxf(acc[mi][ni][1] * sv[ni].y + bv[ni].y, -100.f), 100.f);
            o1.x = fminf(fmaxf(acc[mi][ni][2] * sv[ni].x + bv[ni].x, -100.f), 100.f);
            o1.y = fminf(fmaxf(acc[mi][ni][3] * sv[ni].y + bv[ni].y, -100.f), 100.f);
            *reinterpret_cast<float2*>(out + (size_t)row0 * UNITS + col) = o0;
            *reinterpret_cast<float2*>(out + (size_t)(row0 + 8) * UNITS + col) = o1;
        }
    }
}

// ---------------------------------------------------------------- host launch
typedef CUresult (*EncodeTiledFn)(CUtensorMap*, CUtensorMapDataType, cuuint32_t, void*,
                                  const cuuint64_t*, const cuuint64_t*,
                                  const cuuint32_t*, const cuuint32_t*,
                                  CUtensorMapInterleave, CUtensorMapSwizzle,
                                  CUtensorMapL2promotion, CUtensorMapFloatOOBfill);

extern "C" void kernel_launch(void* const* d_in, const int* in_sizes, int n_in,
                              void* d_out, int out_size) {
    const float* x     = (const float*)d_in[0];
    const int4*  pw    = (const int4*)d_in[1];       // uint8 upcast to int32 by harness
    const float* scale = (const float*)d_in[2];
    const float* bias  = (const float*)d_in[3];
    float*       out   = (float*)d_out;

    cvt_x_kernel<<<(MROWS * INFEAT / 4) / 256, 256>>>((const float4*)x);
    unpack_w_kernel<<<(UNITS * INFEAT / 4) / 256, 256>>>(pw);

    void* fnp = nullptr;
    cudaDriverEntryPointQueryResult qres;
    cudaError_t e = cudaGetDriverEntryPointByVersion(
        "cuTensorMapEncodeTiled", &fnp, 12000, cudaEnableDefault, &qres);
    if (e != cudaSuccess || fnp == nullptr) {
        cudaGetDriverEntryPoint("cuTensorMapEncodeTiled", &fnp,
                                cudaEnableDefault, &qres);
    }
    EncodeTiledFn enc = (EncodeTiledFn)fnp;

    void *pXh = nullptr, *pWh = nullptr;
    cudaGetSymbolAddress(&pXh, g_Xh);
    cudaGetSymbolAddress(&pWh, g_Wh);

    CUtensorMap tmA, tmB;
    cuuint64_t dimsA[2]   = {INFEAT, MROWS};
    cuuint64_t dimsB[2]   = {INFEAT, UNITS};
    cuuint64_t strides[1] = {INFEAT * 2};           // row stride in bytes
    cuuint32_t box[2]     = {KC, CTAM};             // 64 fp16 = 128B (SW128), 128 rows
    cuuint32_t es[2]      = {1, 1};
    enc(&tmA, CU_TENSOR_MAP_DATA_TYPE_FLOAT16, 2, pXh, dimsA, strides, box, es,
        CU_TENSOR_MAP_INTERLEAVE_NONE, CU_TENSOR_MAP_SWIZZLE_128B,
        CU_TENSOR_MAP_L2_PROMOTION_L2_128B, CU_TENSOR_MAP_FLOAT_OOB_FILL_NONE);
    enc(&tmB, CU_TENSOR_MAP_DATA_TYPE_FLOAT16, 2, pWh, dimsB, strides, box, es,
        CU_TENSOR_MAP_INTERLEAVE_NONE, CU_TENSOR_MAP_SWIZZLE_128B,
        CU_TENSOR_MAP_L2_PROMOTION_L2_128B, CU_TENSOR_MAP_FLOAT_OOB_FILL_NONE);

    cudaFuncSetAttribute(gemm_kernel, cudaFuncAttributeMaxDynamicSharedMemorySize, SMEM_BYTES);
    gemm_kernel<<<dim3(MROWS / CTAM, UNITS / CTAN), NTHREADS, SMEM_BYTES>>>(
        tmA, tmB, scale, bias, out);
}

// round 10
// speedup vs baseline: 1.0065x; 1.0065x over previous
#include <cuda_runtime.h>
#include <cuda.h>
#include <cuda_fp16.h>
#include <cstdint>

#define MROWS   8192
#define UNITS   4096
#define INFEAT  4096

// GEMM tiling: CTA 128x128x64, 8 compute warps (2x4, warp tile 64x32) + 1 TMA warp
#define CTAM 128
#define CTAN 128
#define KC   64
#define NSTAGE 4
#define STAGE_A_BYTES 16384          // 128 rows x 128B
#define STAGE_BYTES   32768          // A + B
#define SMEM_BYTES (1024 + NSTAGE * STAGE_BYTES)
#define NTHREADS 288

// Scratch (allocation-free rule: __device__ globals)
__device__ __align__(1024) __half g_Xh[(size_t)MROWS * INFEAT];   // 64 MB
__device__ __align__(1024) __half g_Wh[(size_t)UNITS * INFEAT];   // 32 MB

// ---------------------------------------------------------------- utilities
static __device__ __forceinline__ uint32_t smem_u32(const void* p) {
    uint32_t a;
    asm("{ .reg .u64 t; cvta.to.shared.u64 t, %1; cvt.u32.u64 %0, t; }"
        : "=r"(a) : "l"(p));
    return a;
}

#define MBARRIER_INIT(addr, cnt) \
    asm volatile("mbarrier.init.shared.b64 [%0], %1;" :: "r"(addr), "r"(cnt) : "memory")
#define MBARRIER_EXPECT_TX(addr, bytes) \
    asm volatile("mbarrier.arrive.expect_tx.shared.b64 _, [%0], %1;" \
                 :: "r"(addr), "r"(bytes) : "memory")
#define MBARRIER_ARRIVE(addr) \
    asm volatile("mbarrier.arrive.shared.b64 _, [%0];" :: "r"(addr) : "memory")

static __device__ __forceinline__ void mbar_wait(uint32_t addr, uint32_t parity) {
    asm volatile(
        "{\n\t.reg .pred P;\n\t"
        "LAB_WAIT_%=:\n\t"
        "mbarrier.try_wait.parity.acquire.cta.shared::cta.b64 P, [%0], %1, 0x989680;\n\t"
        "@P bra.uni LAB_DONE_%=;\n\t"
        "bra.uni LAB_WAIT_%=;\n\t"
        "LAB_DONE_%=:\n\t}"
        :: "r"(addr), "r"(parity) : "memory");
}

static __device__ __forceinline__ void tma2d(uint32_t dst, const CUtensorMap* tm,
                                             int cx, int cy, uint32_t mbar) {
    asm volatile(
        "cp.async.bulk.tensor.2d.shared::cta.global.tile.mbarrier::complete_tx::bytes "
        "[%0], [%1, {%2, %3}], [%4];"
        :: "r"(dst), "l"(tm), "r"(cx), "r"(cy), "r"(mbar) : "memory");
}

#define LDSM_X4(r0, r1, r2, r3, a) \
    asm volatile("ldmatrix.sync.aligned.m8n8.x4.shared.b16 {%0,%1,%2,%3}, [%4];" \
                 : "=r"(r0), "=r"(r1), "=r"(r2), "=r"(r3) : "r"(a))

#define MMA16816(c, a0, a1, a2, a3, b0, b1) \
    asm volatile("mma.sync.aligned.m16n8k16.row.col.f32.f16.f16.f32 " \
                 "{%0,%1,%2,%3}, {%4,%5,%6,%7}, {%8,%9}, {%0,%1,%2,%3};" \
                 : "+f"((c)[0]), "+f"((c)[1]), "+f"((c)[2]), "+f"((c)[3]) \
                 : "r"(a0), "r"(a1), "r"(a2), "r"(a3), "r"(b0), "r"(b1))

// ---------------------------------------------------------------- prep kernels

// x fp32 -> fp16 (33.5M elems, 4/thread)
__global__ void cvt_x_kernel(const float4* __restrict__ x) {
    int i = blockIdx.x * blockDim.x + threadIdx.x;
    float4 v = x[i];
    __half2 a = __floats2half2_rn(v.x, v.y);
    __half2 b = __floats2half2_rn(v.z, v.w);
    uint2 o;
    o.x = *reinterpret_cast<uint32_t*>(&a);
    o.y = *reinterpret_cast<uint32_t*>(&b);
    reinterpret_cast<uint2*>(g_Xh)[i] = o;
}

// Unpack 2-bit ternary planes -> fp16 W[u][i].
// pw arrives as int32 (harness upcasts uint8): ONE packed byte per 32-bit word.
// w[u][i] = ((pw32[(u%1024)*4096 + i] >> (2*(u/1024))) & 3) - 1
__global__ void unpack_w_kernel(const int4* __restrict__ pw) {
    int t  = blockIdx.x * blockDim.x + threadIdx.x;   // 0 .. 4194303 (4 halfs each)
    int u  = t >> 10;
    int sh = (u >> 10) * 2;
    int4 v = pw[((u & 1023) << 10) + (t & 1023)];     // 4 packed bytes (as int32s)
    const uint64_t LUT = 0x40003C000000BC00ull;       // {-1,0,1,2} as fp16
    uint32_t c0 = ((uint32_t)v.x >> sh) & 3;
    uint32_t c1 = ((uint32_t)v.y >> sh) & 3;
    uint32_t c2 = ((uint32_t)v.z >> sh) & 3;
    uint32_t c3 = ((uint32_t)v.w >> sh) & 3;
    uint32_t lo = (uint32_t)((LUT >> (c0 << 4)) & 0xFFFF) |
                  ((uint32_t)((LUT >> (c1 << 4)) & 0xFFFF) << 16);
    uint32_t hi = (uint32_t)((LUT >> (c2 << 4)) & 0xFFFF) |
                  ((uint32_t)((LUT >> (c3 << 4)) & 0xFFFF) << 16);
    reinterpret_cast<uint2*>(g_Wh)[t] = make_uint2(lo, hi);
}

// ---------------------------------------------------------------- GEMM kernel
__global__ void __launch_bounds__(NTHREADS, 1) gemm_kernel(
    const __grid_constant__ CUtensorMap tmA,
    const __grid_constant__ CUtensorMap tmB,
    const float* __restrict__ scale, const float* __restrict__ bias,
    float* __restrict__ out)
{
    extern __shared__ __align__(1024) char smem[];
    const uint32_t sb = smem_u32(smem);
    const int tid = threadIdx.x, wid = tid >> 5, lane = tid & 31;
    const int m_base = blockIdx.x * CTAM, n_base = blockIdx.y * CTAN;

    const uint32_t FULL0 = sb, EMPTY0 = sb + 64, STAGE0 = sb + 1024;

    if (tid == 0) {
        for (int s = 0; s < NSTAGE; s++) {
            MBARRIER_INIT(FULL0 + 8 * s, 1);
            MBARRIER_INIT(EMPTY0 + 8 * s, 256);   // 8 compute warps arrive
        }
        asm volatile("fence.proxy.async.shared::cta;" ::: "memory");
    }
    __syncthreads();

    if (wid == 8) {
        // ---- producer: TMA warp ----
        if (lane == 0) {
            for (int i = 0; i < 64; i++) {
                int s = i & 3;
                if (i >= NSTAGE) mbar_wait(EMPTY0 + 8 * s, ((i >> 2) + 1) & 1);
                MBARRIER_EXPECT_TX(FULL0 + 8 * s, STAGE_BYTES);
                uint32_t dst = STAGE0 + s * STAGE_BYTES;
                tma2d(dst,                 &tmA, i * KC, m_base, FULL0 + 8 * s);
                tma2d(dst + STAGE_A_BYTES, &tmB, i * KC, n_base, FULL0 + 8 * s);
            }
        }
        return;
    }

    // ---- compute warps 0-7, warp tile 64x32 at (mw*64, nw*32) ----
    const int mw = wid >> 2, nw = wid & 3;
    const int m0 = mw * 64, n0 = nw * 32;

    // ldmatrix lane address components (SW128 at 128B pitch: addr ^= (row&7)<<4)
    const int rowA  = lane & 15;            // + m0 + mi*16
    const int coffA = (lane >> 4) << 4;     // byte col within 32B k16-slab
    const int swzA  = (rowA & 7) << 4;
    const int rowB  = (((lane >> 4) & 1) << 3) + (lane & 7);  // + n0 + nj*16
    const int coffB = ((lane >> 3) & 1) << 4;
    const int swzB  = (rowB & 7) << 4;

    float acc[4][4][4];
#pragma unroll
    for (int mi = 0; mi < 4; mi++)
#pragma unroll
        for (int ni = 0; ni < 4; ni++)
#pragma unroll
            for (int e = 0; e < 4; e++) acc[mi][ni][e] = 0.f;

    // double-buffered ldmatrix fragments (software pipeline, 1 k16 ahead)
    uint32_t afr[2][4][4], bfr[2][2][4];

    auto load_frags = [&](uint32_t aBase, uint32_t bBase, int k16, int buf) {
#pragma unroll
        for (int mi = 0; mi < 4; mi++) {
            uint32_t ad = aBase + (m0 + mi * 16 + rowA) * 128 +
                          ((k16 * 32 + coffA) ^ swzA);
            LDSM_X4(afr[buf][mi][0], afr[buf][mi][1], afr[buf][mi][2], afr[buf][mi][3], ad);
        }
#pragma unroll
        for (int nj = 0; nj < 2; nj++) {
            uint32_t bd = bBase + (n0 + nj * 16 + rowB) * 128 +
                          ((k16 * 32 + coffB) ^ swzB);
            LDSM_X4(bfr[buf][nj][0], bfr[buf][nj][1], bfr[buf][nj][2], bfr[buf][nj][3], bd);
        }
    };
    auto mma_block = [&](int buf) {
#pragma unroll
        for (int mi = 0; mi < 4; mi++) {
#pragma unroll
            for (int ni = 0; ni < 4; ni++) {
                const uint32_t* bf = &bfr[buf][ni >> 1][(ni & 1) << 1];
                MMA16816(acc[mi][ni], afr[buf][mi][0], afr[buf][mi][1],
                         afr[buf][mi][2], afr[buf][mi][3], bf[0], bf[1]);
            }
        }
    };

    // prologue: wait stage 0, load its first fragments
    mbar_wait(FULL0, 0);
    load_frags(STAGE0, STAGE0 + STAGE_A_BYTES, 0, 0);

    for (int i = 0; i < 64; i++) {
        int s = i & 3;
        uint32_t aBase = STAGE0 + s * STAGE_BYTES;
        uint32_t bBase = aBase + STAGE_A_BYTES;
        // buf is 0 at every iteration start (4 toggles per iteration)
#pragma unroll
        for (int k16 = 0; k16 < 4; k16++) {
            int buf = k16 & 1, nb = buf ^ 1;
            if (k16 < 3)
                load_frags(aBase, bBase, k16 + 1, nb);   // prefetch next k16
            mma_block(buf);                              // consume current frags
            if (k16 == 3) {
                // mma_block above consumed the last frags of this stage ->
                // all LDSM reads of stage s have completed; safe to release.
                MBARRIER_ARRIVE(EMPTY0 + 8 * s);
                if (i < 63) {
                    int s2 = (i + 1) & 3;
                    mbar_wait(FULL0 + 8 * s2, ((i + 1) >> 2) & 1);
                    load_frags(STAGE0 + s2 * STAGE_BYTES,
                               STAGE0 + s2 * STAGE_BYTES + STAGE_A_BYTES, 0, nb);
                }
            }
        }
    }

    // ---- epilogue: scale/bias/clip, direct to gmem ----
    const int gr = lane >> 2, tc = (lane & 3) << 1;
    float2 sv[4], bv[4];
#pragma unroll
    for (int ni = 0; ni < 4; ni++) {
        int col = n_base + n0 + ni * 8 + tc;
        sv[ni] = __ldg((const float2*)(scale + col));
        bv[ni] = __ldg((const float2*)(bias + col));
    }
#pragma unroll
    for (int mi = 0; mi < 4; mi++) {
        int row0 = m_base + m0 + mi * 16 + gr;
#pragma unroll
        for (int ni = 0; ni < 4; ni++) {
            int col = n_base + n0 + ni * 8 + tc;
            float2 o0, o1;
            o0.x = fminf(fmaxf(acc[mi][ni][0] * sv[ni].x + bv[ni].x, -100.f), 100.f);
            o0.y = fminf(fmaxf(acc[mi][ni][1] * sv[ni].y + bv[ni].y, -100.f), 100.f);
            o1.x = fminf(fmaxf(acc[mi][ni][2] * sv[ni].x + bv[ni].x, -100.f), 100.f);
            o1.y = fminf(fmaxf(acc[mi][ni][3] * sv[ni].y + bv[ni].y, -100.f), 100.f);
            *reinterpret_cast<float2*>(out + (size_t)row0 * UNITS + col) = o0;
            *reinterpret_cast<float2*>(out + (size_t)(row0 + 8) * UNITS + col) = o1;
        }
    }
}

// ---------------------------------------------------------------- host launch
typedef CUresult (*EncodeTiledFn)(CUtensorMap*, CUtensorMapDataType, cuuint32_t, void*,
                                  const cuuint64_t*, const cuuint64_t*,
                                  const cuuint32_t*, const cuuint32_t*,
                                  CUtensorMapInterleave, CUtensorMapSwizzle,
                                  CUtensorMapL2promotion, CUtensorMapFloatOOBfill);

extern "C" void kernel_launch(void* const* d_in, const int* in_sizes, int n_in,
                              void* d_out, int out_size) {
    const float* x     = (const float*)d_in[0];
    const int4*  pw    = (const int4*)d_in[1];       // uint8 upcast to int32 by harness
    const float* scale = (const float*)d_in[2];
    const float* bias  = (const float*)d_in[3];
    float*       out   = (float*)d_out;

    cvt_x_kernel<<<(MROWS * INFEAT / 4) / 256, 256>>>((const float4*)x);
    unpack_w_kernel<<<(UNITS * INFEAT / 4) / 256, 256>>>(pw);

    void* fnp = nullptr;
    cudaDriverEntryPointQueryResult qres;
    cudaError_t e = cudaGetDriverEntryPointByVersion(
        "cuTensorMapEncodeTiled", &fnp, 12000, cudaEnableDefault, &qres);
    if (e != cudaSuccess || fnp == nullptr) {
        cudaGetDriverEntryPoint("cuTensorMapEncodeTiled", &fnp,
                                cudaEnableDefault, &qres);
    }
    EncodeTiledFn enc = (EncodeTiledFn)fnp;

    void *pXh = nullptr, *pWh = nullptr;
    cudaGetSymbolAddress(&pXh, g_Xh);
    cudaGetSymbolAddress(&pWh, g_Wh);

    CUtensorMap tmA, tmB;
    cuuint64_t dimsA[2]   = {INFEAT, MROWS};
    cuuint64_t dimsB[2]   = {INFEAT, UNITS};
    cuuint64_t strides[1] = {INFEAT * 2};           // row stride in bytes
    cuuint32_t box[2]     = {KC, CTAM};             // 64 fp16 = 128B (SW128), 128 rows
    cuuint32_t es[2]      = {1, 1};
    enc(&tmA, CU_TENSOR_MAP_DATA_TYPE_FLOAT16, 2, pXh, dimsA, strides, box, es,
        CU_TENSOR_MAP_INTERLEAVE_NONE, CU_TENSOR_MAP_SWIZZLE_128B,
        CU_TENSOR_MAP_L2_PROMOTION_L2_128B, CU_TENSOR_MAP_FLOAT_OOB_FILL_NONE);
    enc(&tmB, CU_TENSOR_MAP_DATA_TYPE_FLOAT16, 2, pWh, dimsB, strides, box, es,
        CU_TENSOR_MAP_INTERLEAVE_NONE, CU_TENSOR_MAP_SWIZZLE_128B,
        CU_TENSOR_MAP_L2_PROMOTION_L2_128B, CU_TENSOR_MAP_FLOAT_OOB_FILL_NONE);

    cudaFuncSetAttribute(gemm_kernel, cudaFuncAttributeMaxDynamicSharedMemorySize, SMEM_BYTES);
    gemm_kernel<<<dim3(MROWS / CTAM, UNITS / CTAN), NTHREADS, SMEM_BYTES>>>(
        tmA, tmB, scale, bias, out);
}

// round 11
// speedup vs baseline: 1.0453x; 1.0385x over previous
#include <cuda_runtime.h>
#include <cuda.h>
#include <cuda_fp16.h>
#include <cstdint>

#define MROWS   8192
#define UNITS   4096
#define INFEAT  4096

// GEMM tiling: CTA 256x128x64, 8 compute warps (2x4, warp tile 128x32) + 1 TMA warp
#define CTAM 256
#define CTAN 128
#define KC   64
#define NSTAGE 4
#define STAGE_A_BYTES 32768          // 256 rows x 128B
#define STAGE_B_BYTES 16384          // 128 rows x 128B
#define STAGE_BYTES   49152          // A + B
#define SMEM_BYTES (1024 + NSTAGE * STAGE_BYTES)
#define NTHREADS 288

// Scratch (allocation-free rule: __device__ globals)
__device__ __align__(1024) __half g_Xh[(size_t)MROWS * INFEAT];   // 64 MB
__device__ __align__(1024) __half g_Wh[(size_t)UNITS * INFEAT];   // 32 MB

// ---------------------------------------------------------------- utilities
static __device__ __forceinline__ uint32_t smem_u32(const void* p) {
    uint32_t a;
    asm("{ .reg .u64 t; cvta.to.shared.u64 t, %1; cvt.u32.u64 %0, t; }"
        : "=r"(a) : "l"(p));
    return a;
}

#define MBARRIER_INIT(addr, cnt) \
    asm volatile("mbarrier.init.shared.b64 [%0], %1;" :: "r"(addr), "r"(cnt) : "memory")
#define MBARRIER_EXPECT_TX(addr, bytes) \
    asm volatile("mbarrier.arrive.expect_tx.shared.b64 _, [%0], %1;" \
                 :: "r"(addr), "r"(bytes) : "memory")
#define MBARRIER_ARRIVE(addr) \
    asm volatile("mbarrier.arrive.shared.b64 _, [%0];" :: "r"(addr) : "memory")

static __device__ __forceinline__ void mbar_wait(uint32_t addr, uint32_t parity) {
    asm volatile(
        "{\n\t.reg .pred P;\n\t"
        "LAB_WAIT_%=:\n\t"
        "mbarrier.try_wait.parity.acquire.cta.shared::cta.b64 P, [%0], %1, 0x989680;\n\t"
        "@P bra.uni LAB_DONE_%=;\n\t"
        "bra.uni LAB_WAIT_%=;\n\t"
        "LAB_DONE_%=:\n\t}"
        :: "r"(addr), "r"(parity) : "memory");
}

static __device__ __forceinline__ void tma2d(uint32_t dst, const CUtensorMap* tm,
                                             int cx, int cy, uint32_t mbar) {
    asm volatile(
        "cp.async.bulk.tensor.2d.shared::cta.global.tile.mbarrier::complete_tx::bytes "
        "[%0], [%1, {%2, %3}], [%4];"
        :: "r"(dst), "l"(tm), "r"(cx), "r"(cy), "r"(mbar) : "memory");
}

#define LDSM_X4(r0, r1, r2, r3, a) \
    asm volatile("ldmatrix.sync.aligned.m8n8.x4.shared.b16 {%0,%1,%2,%3}, [%4];" \
                 : "=r"(r0), "=r"(r1), "=r"(r2), "=r"(r3) : "r"(a))

#define MMA16816(c, a0, a1, a2, a3, b0, b1) \
    asm volatile("mma.sync.aligned.m16n8k16.row.col.f32.f16.f16.f32 " \
                 "{%0,%1,%2,%3}, {%4,%5,%6,%7}, {%8,%9}, {%0,%1,%2,%3};" \
                 : "+f"((c)[0]), "+f"((c)[1]), "+f"((c)[2]), "+f"((c)[3]) \
                 : "r"(a0), "r"(a1), "r"(a2), "r"(a3), "r"(b0), "r"(b1))

// ---------------------------------------------------------------- prep kernel
// Merged: blocks [0, 32768) convert x fp32->fp16; blocks [32768, 49152) unpack W.
__global__ void prep_kernel(const float4* __restrict__ x, const int4* __restrict__ pw) {
    int b = blockIdx.x;
    if (b < 32768) {
        // x fp32 -> fp16, 4 elems/thread
        int i = b * 256 + threadIdx.x;
        float4 v = x[i];
        __half2 a = __floats2half2_rn(v.x, v.y);
        __half2 c = __floats2half2_rn(v.z, v.w);
        uint2 o;
        o.x = *reinterpret_cast<uint32_t*>(&a);
        o.y = *reinterpret_cast<uint32_t*>(&c);
        reinterpret_cast<uint2*>(g_Xh)[i] = o;
    } else {
        // Unpack 2-bit ternary planes -> fp16 W[u][i].
        // pw arrives as int32 (harness upcasts uint8): one packed byte per word.
        // w[u][i] = ((pw32[(u%1024)*4096 + i] >> (2*(u/1024))) & 3) - 1
        int t  = (b - 32768) * 256 + threadIdx.x;     // 0 .. 4194303 (4 halfs each)
        int u  = t >> 10;
        int sh = (u >> 10) * 2;
        int4 v = pw[((u & 1023) << 10) + (t & 1023)];
        const uint64_t LUT = 0x40003C000000BC00ull;   // {-1,0,1,2} as fp16
        uint32_t c0 = ((uint32_t)v.x >> sh) & 3;
        uint32_t c1 = ((uint32_t)v.y >> sh) & 3;
        uint32_t c2 = ((uint32_t)v.z >> sh) & 3;
        uint32_t c3 = ((uint32_t)v.w >> sh) & 3;
        uint32_t lo = (uint32_t)((LUT >> (c0 << 4)) & 0xFFFF) |
                      ((uint32_t)((LUT >> (c1 << 4)) & 0xFFFF) << 16);
        uint32_t hi = (uint32_t)((LUT >> (c2 << 4)) & 0xFFFF) |
                      ((uint32_t)((LUT >> (c3 << 4)) & 0xFFFF) << 16);
        reinterpret_cast<uint2*>(g_Wh)[t] = make_uint2(lo, hi);
    }
}

// ---------------------------------------------------------------- GEMM kernel
__global__ void __launch_bounds__(NTHREADS, 1) gemm_kernel(
    const __grid_constant__ CUtensorMap tmA,
    const __grid_constant__ CUtensorMap tmB,
    const float* __restrict__ scale, const float* __restrict__ bias,
    float* __restrict__ out)
{
    extern __shared__ __align__(1024) char smem[];
    const uint32_t sb = smem_u32(smem);
    const int tid = threadIdx.x, wid = tid >> 5, lane = tid & 31;
    const int m_base = blockIdx.x * CTAM, n_base = blockIdx.y * CTAN;

    const uint32_t FULL0 = sb, EMPTY0 = sb + 64, STAGE0 = sb + 1024;

    if (tid == 0) {
        for (int s = 0; s < NSTAGE; s++) {
            MBARRIER_INIT(FULL0 + 8 * s, 1);
            MBARRIER_INIT(EMPTY0 + 8 * s, 256);   // 8 compute warps arrive
        }
        asm volatile("fence.proxy.async.shared::cta;" ::: "memory");
    }
    __syncthreads();

    if (wid == 8) {
        // ---- producer: TMA warp ----
        if (lane == 0) {
            for (int i = 0; i < 64; i++) {
                int s = i & 3;
                if (i >= NSTAGE) mbar_wait(EMPTY0 + 8 * s, ((i >> 2) + 1) & 1);
                MBARRIER_EXPECT_TX(FULL0 + 8 * s, STAGE_BYTES);
                uint32_t dst = STAGE0 + s * STAGE_BYTES;
                tma2d(dst,                 &tmA, i * KC, m_base, FULL0 + 8 * s);
                tma2d(dst + STAGE_A_BYTES, &tmB, i * KC, n_base, FULL0 + 8 * s);
            }
        }
        return;
    }

    // ---- compute warps 0-7, warp tile 128x32 at (mw*128, nw*32) ----
    const int mw = wid >> 2, nw = wid & 3;
    const int m0 = mw * 128, n0 = nw * 32;

    // ldmatrix lane address components (SW128 at 128B pitch: addr ^= (row&7)<<4)
    const int rowA  = lane & 15;            // + m0 + mi*16
    const int coffA = (lane >> 4) << 4;     // byte col within 32B k16-slab
    const int swzA  = (rowA & 7) << 4;
    const int rowB  = (((lane >> 4) & 1) << 3) + (lane & 7);  // + n0 + nj*16
    const int coffB = ((lane >> 3) & 1) << 4;
    const int swzB  = (rowB & 7) << 4;

    float acc[8][4][4];
#pragma unroll
    for (int mi = 0; mi < 8; mi++)
#pragma unroll
        for (int ni = 0; ni < 4; ni++)
#pragma unroll
            for (int e = 0; e < 4; e++) acc[mi][ni][e] = 0.f;

    for (int i = 0; i < 64; i++) {
        int s = i & 3;
        mbar_wait(FULL0 + 8 * s, (i >> 2) & 1);
        uint32_t aBase = STAGE0 + s * STAGE_BYTES;
        uint32_t bBase = aBase + STAGE_A_BYTES;
#pragma unroll
        for (int k16 = 0; k16 < 4; k16++) {
            uint32_t a[8][4], b[2][4];
#pragma unroll
            for (int mi = 0; mi < 8; mi++) {
                uint32_t ad = aBase + (m0 + mi * 16 + rowA) * 128 +
                              ((k16 * 32 + coffA) ^ swzA);
                LDSM_X4(a[mi][0], a[mi][1], a[mi][2], a[mi][3], ad);
            }
#pragma unroll
            for (int nj = 0; nj < 2; nj++) {
                uint32_t bd = bBase + (n0 + nj * 16 + rowB) * 128 +
                              ((k16 * 32 + coffB) ^ swzB);
                LDSM_X4(b[nj][0], b[nj][1], b[nj][2], b[nj][3], bd);
            }
#pragma unroll
            for (int mi = 0; mi < 8; mi++) {
#pragma unroll
                for (int ni = 0; ni < 4; ni++) {
                    const uint32_t* bf = &b[ni >> 1][(ni & 1) << 1];
                    MMA16816(acc[mi][ni], a[mi][0], a[mi][1], a[mi][2], a[mi][3],
                             bf[0], bf[1]);
                }
            }
        }
        MBARRIER_ARRIVE(EMPTY0 + 8 * s);
    }

    // ---- epilogue: scale/bias/clip, direct to gmem ----
    const int gr = lane >> 2, tc = (lane & 3) << 1;
    float2 sv[4], bv[4];
#pragma unroll
    for (int ni = 0; ni < 4; ni++) {
        int col = n_base + n0 + ni * 8 + tc;
        sv[ni] = __ldg((const float2*)(scale + col));
        bv[ni] = __ldg((const float2*)(bias + col));
    }
#pragma unroll
    for (int mi = 0; mi < 8; mi++) {
        int row0 = m_base + m0 + mi * 16 + gr;
#pragma unroll
        for (int ni = 0; ni < 4; ni++) {
            int col = n_base + n0 + ni * 8 + tc;
            float2 o0, o1;
            o0.x = fminf(fmaxf(acc[mi][ni][0] * sv[ni].x + bv[ni].x, -100.f), 100.f);
            o0.y = fminf(fmaxf(acc[mi][ni][1] * sv[ni].y + bv[ni].y, -100.f), 100.f);
            o1.x = fminf(fmaxf(acc[mi][ni][2] * sv[ni].x + bv[ni].x, -100.f), 100.f);
            o1.y = fminf(fmaxf(acc[mi][ni][3] * sv[ni].y + bv[ni].y, -100.f), 100.f);
            *reinterpret_cast<float2*>(out + (size_t)row0 * UNITS + col) = o0;
            *reinterpret_cast<float2*>(out + (size_t)(row0 + 8) * UNITS + col) = o1;
        }
    }
}

// ---------------------------------------------------------------- host launch
typedef CUresult (*EncodeTiledFn)(CUtensorMap*, CUtensorMapDataType, cuuint32_t, void*,
                                  const cuuint64_t*, const cuuint64_t*,
                                  const cuuint32_t*, const cuuint32_t*,
                                  CUtensorMapInterleave, CUtensorMapSwizzle,
                                  CUtensorMapL2promotion, CUtensorMapFloatOOBfill);

extern "C" void kernel_launch(void* const* d_in, const int* in_sizes, int n_in,
                              void* d_out, int out_size) {
    const float* x     = (const float*)d_in[0];
    const int4*  pw    = (const int4*)d_in[1];       // uint8 upcast to int32 by harness
    const float* scale = (const float*)d_in[2];
    const float* bias  = (const float*)d_in[3];
    float*       out   = (float*)d_out;

    prep_kernel<<<49152, 256>>>((const float4*)x, pw);

    void* fnp = nullptr;
    cudaDriverEntryPointQueryResult qres;
    cudaError_t e = cudaGetDriverEntryPointByVersion(
        "cuTensorMapEncodeTiled", &fnp, 12000, cudaEnableDefault, &qres);
    if (e != cudaSuccess || fnp == nullptr) {
        cudaGetDriverEntryPoint("cuTensorMapEncodeTiled", &fnp,
                                cudaEnableDefault, &qres);
    }
    EncodeTiledFn enc = (EncodeTiledFn)fnp;

    void *pXh = nullptr, *pWh = nullptr;
    cudaGetSymbolAddress(&pXh, g_Xh);
    cudaGetSymbolAddress(&pWh, g_Wh);

    CUtensorMap tmA, tmB;
    cuuint64_t dimsA[2]   = {INFEAT, MROWS};
    cuuint64_t dimsB[2]   = {INFEAT, UNITS};
    cuuint64_t strides[1] = {INFEAT * 2};           // row stride in bytes
    cuuint32_t boxA[2]    = {KC, CTAM};             // 64 fp16 = 128B (SW128), 256 rows
    cuuint32_t boxB[2]    = {KC, CTAN};             // 128 rows
    cuuint32_t es[2]      = {1, 1};
    enc(&tmA, CU_TENSOR_MAP_DATA_TYPE_FLOAT16, 2, pXh, dimsA, strides, boxA, es,
        CU_TENSOR_MAP_INTERLEAVE_NONE, CU_TENSOR_MAP_SWIZZLE_128B,
        CU_TENSOR_MAP_L2_PROMOTION_L2_128B, CU_TENSOR_MAP_FLOAT_OOB_FILL_NONE);
    enc(&tmB, CU_TENSOR_MAP_DATA_TYPE_FLOAT16, 2, pWh, dimsB, strides, boxB, es,
        CU_TENSOR_MAP_INTERLEAVE_NONE, CU_TENSOR_MAP_SWIZZLE_128B,
        CU_TENSOR_MAP_L2_PROMOTION_L2_128B, CU_TENSOR_MAP_FLOAT_OOB_FILL_NONE);

    cudaFuncSetAttribute(gemm_kernel, cudaFuncAttributeMaxDynamicSharedMemorySize, SMEM_BYTES);
    gemm_kernel<<<dim3(MROWS / CTAM, UNITS / CTAN), NTHREADS, SMEM_BYTES>>>(
        tmA, tmB, scale, bias, out);
}